// round 13
// baseline (speedup 1.0000x reference)
#include <cuda_runtime.h>
#include <cuda_bf16.h>
#include <cuda_fp16.h>
#include <math.h>
#include <stdint.h>

// Problem constants (fixed by the reference)
#define BB 2048
#define EE 512
#define CC 16384
// TEMPERATURE=0.05 -> 1/T = 20; TAU=4 -> scale/TAU: same=0.25, diff=0.125
// ramp = (epoch/150) * 1.0 * 16

// ---------------- device scratch (no allocations allowed) ----------------
__device__ __half         g_batH[BB * EE];          // 2 MB (fp16, for logits GEMM)
__device__ __half         g_cmnH[(size_t)CC * EE];  // 16 MB (normalized class_map fp16)
__device__ __nv_bfloat16  g_bat[BB * EE];           // 2 MB (bf16, for KD GEMM)
__device__ __nv_bfloat16  g_tea[BB * EE];           // 2 MB
__device__ float          g_pm[(size_t)BB * 64];    // per-(row, Ntile) max*20
__device__ float          g_ps[(size_t)BB * 64];    // per-(row, Ntile) sumexp
__device__ float          g_kMx[BB * 16], g_kSx[BB * 16];   // KD partials (student)
__device__ float          g_kMy[BB * 16], g_kSy[BB * 16];   // KD partials (teacher)
__device__ float          g_kU [BB * 16];
__device__ float          g_inv[CC];                // 1/||class_map_row||
__device__ float          g_lablogit[BB];           // fp32 exact label logits
__device__ float          g_rowv[BB];               // per-row (lse - label_logit)
__device__ float          g_kl[BB];                 // per-row KL
__device__ int            g_lab32[BB];              // decoded labels

// ---------------- helpers ----------------
__device__ __forceinline__ void mma16816(float* c, const uint32_t* a, const uint32_t* b) {
    asm volatile(
        "mma.sync.aligned.m16n8k16.row.col.f32.bf16.bf16.f32 "
        "{%0,%1,%2,%3}, {%4,%5,%6,%7}, {%8,%9}, {%0,%1,%2,%3};\n"
        : "+f"(c[0]), "+f"(c[1]), "+f"(c[2]), "+f"(c[3])
        : "r"(a[0]), "r"(a[1]), "r"(a[2]), "r"(a[3]), "r"(b[0]), "r"(b[1]));
}

__device__ __forceinline__ void mma16816h(uint32_t* c, const uint32_t* a, const uint32_t* b) {
    asm volatile(
        "mma.sync.aligned.m16n8k16.row.col.f16.f16.f16.f16 "
        "{%0,%1}, {%2,%3,%4,%5}, {%6,%7}, {%0,%1};\n"
        : "+r"(c[0]), "+r"(c[1])
        : "r"(a[0]), "r"(a[1]), "r"(a[2]), "r"(a[3]), "r"(b[0]), "r"(b[1]));
}

__device__ __forceinline__ void ldsm4(uint32_t* r, uint32_t saddr) {
    asm volatile("ldmatrix.sync.aligned.m8n8.x4.shared.b16 {%0,%1,%2,%3}, [%4];\n"
                 : "=r"(r[0]), "=r"(r[1]), "=r"(r[2]), "=r"(r[3]) : "r"(saddr));
}

__device__ __forceinline__ void cp16(uint32_t saddr, const void* gptr) {
    asm volatile("cp.async.cg.shared.global [%0], [%1], 16;\n" :: "r"(saddr), "l"(gptr));
}

// ---------------- label decode (int32 vs int64 robust) ----------------
__global__ void k_labels(const int* __restrict__ raw) {
    __shared__ int is64;
    if (threadIdx.x == 0) {
        int ok = 1;
        for (int i = 0; i < 64; i++)
            if (raw[2 * i + 1] != 0) { ok = 0; break; }
        is64 = ok;
    }
    __syncthreads();
    int f = is64;
    for (int i = threadIdx.x; i < BB; i += blockDim.x)
        g_lab32[i] = f ? raw[2 * i] : raw[i];
}

// ---------------- class_map: row norm + normalized fp16 convert ----------------
__global__ void k_prep_cm(const float* __restrict__ cmap) {
    int c = blockIdx.x;
    int t = threadIdx.x;
    const float4* row = (const float4*)(cmap + (size_t)c * EE);
    float4 v = row[t];
    float ss = v.x * v.x + v.y * v.y + v.z * v.z + v.w * v.w;
    #pragma unroll
    for (int o = 16; o; o >>= 1) ss += __shfl_xor_sync(0xffffffffu, ss, o);
    __shared__ float sred[4];
    if ((t & 31) == 0) sred[t >> 5] = ss;
    __syncthreads();
    float tot = sred[0] + sred[1] + sred[2] + sred[3];
    float inv = 1.0f / sqrtf(tot);
    if (t == 0) g_inv[c] = inv;
    __half2* drow = (__half2*)(g_cmnH + (size_t)c * EE);
    drow[t * 2 + 0] = __floats2half2_rn(v.x * inv, v.y * inv);
    drow[t * 2 + 1] = __floats2half2_rn(v.z * inv, v.w * inv);
}

// ---------------- batch -> fp16+bf16, teacher -> bf16 ----------------
__global__ void k_prep_vec(const float* __restrict__ batch, const float* __restrict__ teacher) {
    const int n = BB * EE / 4;
    for (int i = blockIdx.x * blockDim.x + threadIdx.x; i < n; i += gridDim.x * blockDim.x) {
        float4 b = ((const float4*)batch)[i];
        ((__half2*)g_batH)[i * 2 + 0] = __floats2half2_rn(b.x, b.y);
        ((__half2*)g_batH)[i * 2 + 1] = __floats2half2_rn(b.z, b.w);
        ((__nv_bfloat162*)g_bat)[i * 2 + 0] = __floats2bfloat162_rn(b.x, b.y);
        ((__nv_bfloat162*)g_bat)[i * 2 + 1] = __floats2bfloat162_rn(b.z, b.w);
        float4 s = ((const float4*)teacher)[i];
        ((__nv_bfloat162*)g_tea)[i * 2 + 0] = __floats2bfloat162_rn(s.x, s.y);
        ((__nv_bfloat162*)g_tea)[i * 2 + 1] = __floats2bfloat162_rn(s.z, s.w);
    }
}

// ---------------- exact fp32 label logit per row (one warp per row) ----------------
__global__ void k_lab(const float* __restrict__ batch, const float* __restrict__ cmap) {
    int gw = (blockIdx.x * blockDim.x + threadIdx.x) >> 5;
    int lane = threadIdx.x & 31;
    if (gw >= BB) return;
    int l = g_lab32[gw];
    const float4* br = (const float4*)(batch + (size_t)gw * EE);
    const float4* cr = (const float4*)(cmap + (size_t)l * EE);
    float s = 0.f;
    #pragma unroll
    for (int i = 0; i < 4; i++) {
        float4 b = br[lane + i * 32];
        float4 c = cr[lane + i * 32];
        s = fmaf(b.x, c.x, s); s = fmaf(b.y, c.y, s);
        s = fmaf(b.z, c.z, s); s = fmaf(b.w, c.w, s);
    }
    #pragma unroll
    for (int o = 16; o; o >>= 1) s += __shfl_xor_sync(0xffffffffu, s, o);
    if (lane == 0) g_lablogit[gw] = s * g_inv[l] * 20.0f;
}

// ---------------- logits GEMM: fp16 in, f16 accumulate, 128x256 tile ----------------
// BK=32, 4-stage cp.async ring, fused per-row (max, sumexp) partials.
#define ST0 4
#define A_ELTS (128 * 40)
#define B_ELTS (256 * 40)
#define STAGE0 (A_ELTS + B_ELTS)

__global__ void __launch_bounds__(256) k_gemm0() {
    extern __shared__ __half dyn0[];

    const int tid = threadIdx.x, lane = tid & 31, wid = tid >> 5;
    const int wm = (wid >> 2) * 64, wn = (wid & 3) * 64;   // warp grid 2(m) x 4(n)
    const int bm = blockIdx.x * 128, bn = blockIdx.y * 256;

    uint32_t acc[4][8][2];
    #pragma unroll
    for (int i = 0; i < 4; i++)
        #pragma unroll
        for (int j = 0; j < 8; j++) { acc[i][j][0] = 0u; acc[i][j][1] = 0u; }

    const uint32_t base = (uint32_t)__cvta_generic_to_shared(dyn0);

    const int lr = tid >> 2, lch = tid & 3;   // lr 0..63, chunk 0..3 (8 halfs)
    auto load_tile = [&](int kt, int buf) {
        uint32_t ab = base + (uint32_t)buf * (STAGE0 * 2);
        uint32_t bb = ab + A_ELTS * 2;
        const __half* xs = g_batH + (size_t)(bm + lr) * EE + kt + lch * 8;
        cp16(ab + (uint32_t)(lr * 40 + lch * 8) * 2, xs);
        cp16(ab + (uint32_t)((lr + 64) * 40 + lch * 8) * 2, xs + (size_t)64 * EE);
        const __half* ys = g_cmnH + (size_t)(bn + lr) * EE + kt + lch * 8;
        #pragma unroll
        for (int j = 0; j < 4; j++)
            cp16(bb + (uint32_t)((lr + j * 64) * 40 + lch * 8) * 2, ys + (size_t)(j * 64) * EE);
        asm volatile("cp.async.commit_group;\n");
    };

    const int aRow = (lane & 15), aCol = (lane >> 4) * 8;
    const int gq = lane >> 3;
    const int bRowBase = ((gq >> 1) << 3) + (lane & 7);
    const int bCol = (gq & 1) << 3;

    const int NT = EE / 32;   // 16

    #pragma unroll
    for (int s = 0; s < ST0 - 1; s++) load_tile(s * 32, s);

    for (int t = 0; t < NT; t++) {
        asm volatile("cp.async.wait_group %0;\n" :: "n"(ST0 - 2));
        __syncthreads();
        if (t + ST0 - 1 < NT) load_tile((t + ST0 - 1) * 32, (t + ST0 - 1) % ST0);
        else asm volatile("cp.async.commit_group;\n");

        uint32_t ab = base + (uint32_t)(t % ST0) * (STAGE0 * 2);
        uint32_t bb = ab + A_ELTS * 2;
        #pragma unroll
        for (int ks = 0; ks < 2; ks++) {
            const int kk = ks * 16;
            uint32_t af[4][4], bf[8][2];
            #pragma unroll
            for (int im = 0; im < 4; im++) {
                int row = wm + im * 16 + aRow;
                ldsm4(af[im], ab + (uint32_t)(row * 40 + kk + aCol) * 2);
            }
            #pragma unroll
            for (int np = 0; np < 4; np++) {
                int nloc = wn + np * 16 + bRowBase;
                uint32_t rr[4];
                ldsm4(rr, bb + (uint32_t)(nloc * 40 + kk + bCol) * 2);
                bf[np * 2 + 0][0] = rr[0]; bf[np * 2 + 0][1] = rr[1];
                bf[np * 2 + 1][0] = rr[2]; bf[np * 2 + 1][1] = rr[3];
            }
            #pragma unroll
            for (int im = 0; im < 4; im++)
                #pragma unroll
                for (int in = 0; in < 8; in++)
                    mma16816h(acc[im][in], af[im], bf[in]);
        }
    }

    // Fused epilogue: per-row (max, sumexp) of 20*acc over this block's 256 cols.
    __syncthreads();
    float2* red = (float2*)dyn0;              // [128][4]
    const int qcol = lane & 3;
    #pragma unroll
    for (int im = 0; im < 4; im++) {
        #pragma unroll
        for (int h = 0; h < 2; h++) {
            float v[16];
            #pragma unroll
            for (int in = 0; in < 8; in++) {
                float2 p = __half22float2(*(__half2*)&acc[im][in][h]);
                v[in * 2 + 0] = p.x * 20.0f;
                v[in * 2 + 1] = p.y * 20.0f;
            }
            float m = -1e30f;
            #pragma unroll
            for (int i = 0; i < 16; i++) m = fmaxf(m, v[i]);
            m = fmaxf(m, __shfl_xor_sync(0xffffffffu, m, 1));
            m = fmaxf(m, __shfl_xor_sync(0xffffffffu, m, 2));
            float s = 0.f;
            #pragma unroll
            for (int i = 0; i < 16; i++) s += __expf(v[i] - m);
            s += __shfl_xor_sync(0xffffffffu, s, 1);
            s += __shfl_xor_sync(0xffffffffu, s, 2);
            if (qcol == 0) {
                int rloc = wm + im * 16 + (lane >> 2) + 8 * h;
                red[rloc * 4 + (wid & 3)] = make_float2(m, s);
            }
        }
    }
    __syncthreads();
    if (tid < 128) {
        float M = -1e30f, S = 0.f;
        #pragma unroll
        for (int w = 0; w < 4; w++) {
            float2 p = red[tid * 4 + w];
            float Mn = fmaxf(M, p.x);
            S = S * __expf(M - Mn) + p.y * __expf(p.x - Mn);
            M = Mn;
        }
        size_t o = (size_t)(bm + tid) * 64 + blockIdx.y;
        g_pm[o] = M;
        g_ps[o] = S;
    }
}

#define GEMM0_SMEM (ST0 * STAGE0 * 2)   // 122880 B

// ---------------- fused sim+tsim GEMM + KD partials (bf16/f32, unchanged) ----------------
#define ST2 3
#define PAN 10240                 // one 128x(32+pad) bf16 panel, bytes
#define SSTR (4 * PAN)            // 4 panels per stage

__global__ void __launch_bounds__(256) k_gemm12() {
    extern __shared__ __nv_bfloat16 dyn[];
    __shared__ float redMx[512], redSx[512], redMy[512], redSy[512], redU[512];
    __shared__ int slabr[128], slabc[128];

    const int tid = threadIdx.x, lane = tid & 31, wid = tid >> 5;
    const int wm = (wid >> 2) * 64, wn = (wid & 3) * 32;
    const int bm = blockIdx.x * 128, bn = blockIdx.y * 128;

    if (tid < 128) slabr[tid] = g_lab32[bm + tid];
    else slabc[tid - 128] = g_lab32[bn + tid - 128];

    float accS[4][4][4], accT[4][4][4];
    #pragma unroll
    for (int i = 0; i < 4; i++)
        #pragma unroll
        for (int j = 0; j < 4; j++)
            #pragma unroll
            for (int k = 0; k < 4; k++) { accS[i][j][k] = 0.f; accT[i][j][k] = 0.f; }

    const uint32_t base = (uint32_t)__cvta_generic_to_shared(dyn);

    const int lr = tid >> 1, lh = tid & 1;
    const uint32_t loff = (uint32_t)(lr * 80 + lh * 32);

    auto load_tile = [&](int kt, int buf) {
        uint32_t sb = base + (uint32_t)buf * SSTR;
        const __nv_bfloat16* s0 = g_bat + (size_t)(bm + lr) * EE + kt + lh * 16;
        const __nv_bfloat16* s1 = g_bat + (size_t)(bn + lr) * EE + kt + lh * 16;
        const __nv_bfloat16* s2 = g_tea + (size_t)(bm + lr) * EE + kt + lh * 16;
        const __nv_bfloat16* s3 = g_tea + (size_t)(bn + lr) * EE + kt + lh * 16;
        cp16(sb + loff, s0);              cp16(sb + loff + 16, s0 + 8);
        cp16(sb + PAN + loff, s1);        cp16(sb + PAN + loff + 16, s1 + 8);
        cp16(sb + 2 * PAN + loff, s2);    cp16(sb + 2 * PAN + loff + 16, s2 + 8);
        cp16(sb + 3 * PAN + loff, s3);    cp16(sb + 3 * PAN + loff + 16, s3 + 8);
        asm volatile("cp.async.commit_group;\n");
    };

    const int aRow = (lane & 15), aCol = (lane >> 4) * 8;
    const int gq = lane >> 3;
    const int bRowBase = ((gq >> 1) << 3) + (lane & 7);
    const int bCol = (gq & 1) << 3;

    const int NT = EE / 32;   // 16

    load_tile(0, 0);
    load_tile(32, 1);

    for (int t = 0; t < NT; t++) {
        asm volatile("cp.async.wait_group %0;\n" :: "n"(ST2 - 2));
        __syncthreads();
        if (t + ST2 - 1 < NT) load_tile((t + ST2 - 1) * 32, (t + ST2 - 1) % ST2);
        else asm volatile("cp.async.commit_group;\n");

        uint32_t sb = base + (uint32_t)(t % ST2) * SSTR;
        #pragma unroll
        for (int ks = 0; ks < 2; ks++) {
            const int kk = ks * 16;
            uint32_t afS[4][4], bfS[4][2], afT[4][4], bfT[4][2];
            #pragma unroll
            for (int im = 0; im < 4; im++) {
                int row = wm + im * 16 + aRow;
                uint32_t ro = (uint32_t)(row * 40 + kk + aCol) * 2;
                ldsm4(afS[im], sb + ro);
                ldsm4(afT[im], sb + 2 * PAN + ro);
            }
            #pragma unroll
            for (int np = 0; np < 2; np++) {
                int nloc = wn + np * 16 + bRowBase;
                uint32_t ro = (uint32_t)(nloc * 40 + kk + bCol) * 2;
                uint32_t rr[4];
                ldsm4(rr, sb + PAN + ro);
                bfS[np * 2 + 0][0] = rr[0]; bfS[np * 2 + 0][1] = rr[1];
                bfS[np * 2 + 1][0] = rr[2]; bfS[np * 2 + 1][1] = rr[3];
                ldsm4(rr, sb + 3 * PAN + ro);
                bfT[np * 2 + 0][0] = rr[0]; bfT[np * 2 + 0][1] = rr[1];
                bfT[np * 2 + 1][0] = rr[2]; bfT[np * 2 + 1][1] = rr[3];
            }
            #pragma unroll
            for (int im = 0; im < 4; im++)
                #pragma unroll
                for (int in = 0; in < 4; in++) {
                    mma16816(accS[im][in], afS[im], bfS[in]);
                    mma16816(accT[im][in], afT[im], bfT[in]);
                }
        }
    }
    __syncthreads();

    const int qrow = lane >> 2, qcol = lane & 3;
    #pragma unroll
    for (int im = 0; im < 4; im++) {
        #pragma unroll
        for (int h = 0; h < 2; h++) {
            int rloc = wm + im * 16 + qrow + 8 * h;
            int labr = slabr[rloc];
            float xs[8], ys[8];
            float mx = -1e30f, my = -1e30f;
            #pragma unroll
            for (int in = 0; in < 4; in++) {
                #pragma unroll
                for (int e = 0; e < 2; e++) {
                    int cl = wn + in * 8 + qcol * 2 + e;
                    float sc = (slabc[cl] == labr) ? 0.25f : 0.125f;
                    float x = accS[im][in][2 * h + e] * sc;
                    float y = accT[im][in][2 * h + e] * sc;
                    xs[in * 2 + e] = x; ys[in * 2 + e] = y;
                    mx = fmaxf(mx, x); my = fmaxf(my, y);
                }
            }
            mx = fmaxf(mx, __shfl_xor_sync(0xffffffffu, mx, 1));
            mx = fmaxf(mx, __shfl_xor_sync(0xffffffffu, mx, 2));
            my = fmaxf(my, __shfl_xor_sync(0xffffffffu, my, 1));
            my = fmaxf(my, __shfl_xor_sync(0xffffffffu, my, 2));
            float sx = 0.f, sy = 0.f, U = 0.f;
            #pragma unroll
            for (int i = 0; i < 8; i++) {
                sx += __expf(xs[i] - mx);
                float e = __expf(ys[i] - my);
                sy += e;
                U += e * (ys[i] - xs[i]);
            }
            sx += __shfl_xor_sync(0xffffffffu, sx, 1);
            sx += __shfl_xor_sync(0xffffffffu, sx, 2);
            sy += __shfl_xor_sync(0xffffffffu, sy, 1);
            sy += __shfl_xor_sync(0xffffffffu, sy, 2);
            U  += __shfl_xor_sync(0xffffffffu, U, 1);
            U  += __shfl_xor_sync(0xffffffffu, U, 2);
            if (qcol == 0) {
                int o = rloc * 4 + (wid & 3);
                redMx[o] = mx; redSx[o] = sx;
                redMy[o] = my; redSy[o] = sy; redU[o] = U;
            }
        }
    }
    __syncthreads();
    if (tid < 128) {
        float Mx = -1e30f, Sx = 0.f, My = -1e30f, Sy = 0.f, U = 0.f;
        #pragma unroll
        for (int w = 0; w < 4; w++) {
            int o = tid * 4 + w;
            float mx2 = redMx[o], sx2 = redSx[o];
            float Mn = fmaxf(Mx, mx2);
            Sx = Sx * __expf(Mx - Mn) + sx2 * __expf(mx2 - Mn);
            Mx = Mn;
            float my2 = redMy[o], sy2 = redSy[o], u2 = redU[o];
            float Myn = fmaxf(My, my2);
            float r1 = __expf(My - Myn), r2 = __expf(my2 - Myn);
            Sy = Sy * r1 + sy2 * r2;
            U  = U  * r1 + u2  * r2;
            My = Myn;
        }
        int o = (bm + tid) * 16 + blockIdx.y;
        g_kMx[o] = Mx; g_kSx[o] = Sx;
        g_kMy[o] = My; g_kSy[o] = Sy; g_kU[o] = U;
    }
}

#define GEMM12_SMEM (ST2 * SSTR)   // 122880 B

// ---------------- merge rank partials (64/row) -> per-row rank value ----------------
__global__ void k_rank() {
    int gw = (blockIdx.x * blockDim.x + threadIdx.x) >> 5;
    int lane = threadIdx.x & 31;
    if (gw >= BB) return;
    const float* pm = g_pm + (size_t)gw * 64;
    const float* ps = g_ps + (size_t)gw * 64;
    float M = -1e30f, S = 0.f;
    #pragma unroll
    for (int i = 0; i < 2; i++) {
        float m2 = pm[lane + i * 32], s2 = ps[lane + i * 32];
        float Mn = fmaxf(M, m2);
        S = S * __expf(M - Mn) + s2 * __expf(m2 - Mn);
        M = Mn;
    }
    #pragma unroll
    for (int o = 16; o; o >>= 1) {
        float m2 = __shfl_xor_sync(0xffffffffu, M, o);
        float s2 = __shfl_xor_sync(0xffffffffu, S, o);
        float Mn = fmaxf(M, m2);
        S = S * __expf(M - Mn) + s2 * __expf(m2 - Mn);
        M = Mn;
    }
    if (lane == 0) g_rowv[gw] = M + logf(S) - g_lablogit[gw];
}

// ---------------- merge KD partials (16 per row) -> per-row KL ----------------
__global__ void k_kdm() {
    int row = (blockIdx.x * blockDim.x + threadIdx.x) >> 5;
    int lane = threadIdx.x & 31;
    if (row >= BB) return;
    float Mx = -1e30f, Sx = 0.f, My = -1e30f, Sy = 0.f, U = 0.f;
    if (lane < 16) {
        int o = row * 16 + lane;
        Mx = g_kMx[o]; Sx = g_kSx[o];
        My = g_kMy[o]; Sy = g_kSy[o]; U = g_kU[o];
    }
    #pragma unroll
    for (int o = 16; o; o >>= 1) {
        float mx2 = __shfl_xor_sync(0xffffffffu, Mx, o);
        float sx2 = __shfl_xor_sync(0xffffffffu, Sx, o);
        float my2 = __shfl_xor_sync(0xffffffffu, My, o);
        float sy2 = __shfl_xor_sync(0xffffffffu, Sy, o);
        float u2  = __shfl_xor_sync(0xffffffffu, U, o);
        float Mn = fmaxf(Mx, mx2);
        Sx = Sx * __expf(Mx - Mn) + sx2 * __expf(mx2 - Mn);
        Mx = Mn;
        float Myn = fmaxf(My, my2);
        float r1 = __expf(My - Myn), r2 = __expf(my2 - Myn);
        Sy = Sy * r1 + sy2 * r2;
        U  = U  * r1 + u2  * r2;
        My = Myn;
    }
    if (lane == 0)
        g_kl[row] = U / Sy + (Mx + logf(Sx)) - (My + logf(Sy));
}

// ---------------- final deterministic reduction ----------------
__global__ void k_final(const int* __restrict__ epoch_raw, int have_epoch,
                        float* __restrict__ out, int out_size) {
    int t = threadIdx.x;
    float a = 0.f, b = 0.f;
    for (int i = t; i < BB; i += 256) { a += g_rowv[i]; b += g_kl[i]; }
    __shared__ float sa[256], sb[256];
    sa[t] = a; sb[t] = b;
    __syncthreads();
    for (int s = 128; s > 0; s >>= 1) {
        if (t < s) { sa[t] += sa[t + s]; sb[t] += sb[t + s]; }
        __syncthreads();
    }
    if (t == 0) {
        float ep = 75.0f;
        if (have_epoch) {
            int iv = epoch_raw[0];
            if (iv >= 0 && iv <= 1000000) ep = (float)iv;
            else ep = __int_as_float(iv);
        }
        float loss_rank = sa[0] * (1.0f / BB);
        float loss_kd   = sb[0] * (1.0f / BB);
        float ramp = (ep / 150.0f) * 16.0f;
        float loss = loss_rank + ramp * loss_kd;
        out[0] = loss;
        if (out_size > 1) out[1] = loss_rank;
        if (out_size > 2) out[2] = loss_kd;
    }
}

// ---------------- launch ----------------
extern "C" void kernel_launch(void* const* d_in, const int* in_sizes, int n_in,
                              void* d_out, int out_size) {
    const float* batch   = (const float*)d_in[0];
    const float* teacher = (const float*)d_in[1];
    const float* cmap    = (const float*)d_in[2];
    const int*   labraw  = (const int*)d_in[3];
    const int*   epochp  = (n_in >= 5) ? (const int*)d_in[4] : (const int*)d_in[3];
    int have_epoch = (n_in >= 5) ? 1 : 0;
    float* out = (float*)d_out;

    cudaFuncSetAttribute(k_gemm0,  cudaFuncAttributeMaxDynamicSharedMemorySize, GEMM0_SMEM);
    cudaFuncSetAttribute(k_gemm12, cudaFuncAttributeMaxDynamicSharedMemorySize, GEMM12_SMEM);

    k_labels<<<1, 256>>>(labraw);
    k_prep_cm<<<CC, 128>>>(cmap);
    k_prep_vec<<<512, 256>>>(batch, teacher);
    k_lab<<<BB / 8, 256>>>(batch, cmap);

    dim3 gL(BB / 128, CC / 256);                 // 16 x 64
    k_gemm0<<<gL, 256, GEMM0_SMEM>>>();
    dim3 gS(BB / 128, BB / 128);                 // 16 x 16
    k_gemm12<<<gS, 256, GEMM12_SMEM>>>();

    k_rank<<<BB / 8, 256>>>();
    k_kdm<<<BB / 8, 256>>>();
    k_final<<<1, 256>>>(epochp, have_epoch, out, out_size);
}